// round 11
// baseline (speedup 1.0000x reference)
#include <cuda_runtime.h>
#include <math.h>
#include <cstdint>

#define NN 50000
#define NE 800000
#define INC 128
#define D 64

typedef unsigned long long ull;

// ---------------- scratch (static device globals; no allocation) ------------
__device__ float g_vq[INC];          // weight_n @ (query @ att_w[:d])
__device__ float g_tk[D];            // key_w @ att_w[d:2d]
__device__ float g_ce;               // weight_e[0,:] . att_w[2d:]
__device__ float g_W1[INC * D];      // weight_n @ out_w[:d]
__device__ float g_hsrc[(size_t)NN * D];
__device__ float g_ka[NN];
__device__ float g_agg[(size_t)NN * D];
__device__ float g_outp[(size_t)NN * D];  // feat_dst @ W1 + bias
__device__ int   g_start[NN + 1];

// ---------------- packed f32x2 helpers (Blackwell FFMA2) --------------------
__device__ __forceinline__ ull pk2(float lo, float hi) {
    ull r;
    asm("mov.b64 %0, {%1, %2};" : "=l"(r) : "f"(lo), "f"(hi));
    return r;
}
__device__ __forceinline__ void fma2(ull& d, ull a, ull b) {
    asm("fma.rn.f32x2 %0, %1, %2, %0;" : "+l"(d) : "l"(a), "l"(b));
}
__device__ __forceinline__ float red2(ull v) {   // lo + hi
    float lo, hi;
    asm("mov.b64 {%0, %1}, %2;" : "=f"(lo), "=f"(hi) : "l"(v));
    return lo + hi;
}

// ---------------- K_prep: fold small mats + segment bounds (one launch) -----
__global__ void k_prep(const float* __restrict__ wn,
                       const float* __restrict__ we,
                       const float* __restrict__ query,
                       const float* __restrict__ key_w,
                       const float* __restrict__ att_w,
                       const float* __restrict__ out_w,
                       const int* __restrict__ dst,
                       int n_nodes, int n_edges) {
    int t = threadIdx.x;
    if (blockIdx.x < 32) {
        int idx = blockIdx.x * 256 + t;      // 8192 outputs of W1
        int k = idx >> 6, c = idx & 63;
        float s = 0.f;
        #pragma unroll 8
        for (int j = 0; j < D; j++) s += wn[k * D + j] * out_w[j * D + c];
        g_W1[idx] = s;
        return;
    }
    if (blockIdx.x > 32) {
        int e = (blockIdx.x - 33) * 256 + t;
        if (e > n_edges) return;
        int d1 = (e < n_edges) ? dst[e] : n_nodes;
        int d0 = (e > 0) ? dst[e - 1] : -1;
        for (int n = d0 + 1; n <= d1; n++) g_start[n] = e;
        return;
    }
    __shared__ float s_aw[3 * D];
    __shared__ float s_tq[D];
    for (int i = t; i < 3 * D; i += 256) s_aw[i] = att_w[i];
    __syncthreads();
    if (t < D) {
        float sq = 0.f, sk = 0.f;
        #pragma unroll 8
        for (int j = 0; j < D; j++) {
            sq += query[t * D + j] * s_aw[j];
            sk += key_w[t * D + j] * s_aw[D + j];
        }
        s_tq[t] = sq;
        g_tk[t] = sk;
    }
    if (t == 64) {
        float c = 0.f;
        for (int j = 0; j < D; j++) c += we[j] * s_aw[2 * D + j];
        g_ce = c;
    }
    __syncthreads();
    if (t < INC) {
        float vq = 0.f;
        #pragma unroll 8
        for (int i = 0; i < D; i++) vq += wn[t * D + i] * s_tq[i];
        g_vq[t] = vq;
    }
}

// ---------------- K_gemm: fused K=128 GEMMs, k-pair f32x2 packing -----------
// blocks [0,nb):   g_hsrc = feat_src @ wn  (+ g_ka epilogue with tk)
// blocks [nb,2nb): g_outp = feat_dst @ W1 + out_b
// 64-row tiles, 256 threads, 2 rows x 8 cols per thread.
// B smem pairs: Bp[kp][c] = (W[2kp][c], W[2kp+1][c]); A operand = raw ull from
// LDG.128 (adjacent k's) -> FFMA2 accumulates even/odd-k partials, no MOV pack.
#define SMG (64 * 64 * 8 + 256)
__global__ void __launch_bounds__(256, 4)
k_gemm(const float* __restrict__ feat_src, const float* __restrict__ feat_dst,
       const float* __restrict__ wn, const float* __restrict__ out_b,
       int n_rows, int nb) {
    extern __shared__ ull Bp[];              // [64 kp][64 c]
    float* s_aux = (float*)(Bp + 64 * 64);
    int t = threadIdx.x;
    bool is_dst = blockIdx.x >= nb;
    const float4* W4 = (const float4*)(is_dst ? g_W1 : wn);
    for (int i = t; i < 64 * 16; i += 256) {
        int kp = i >> 4, c4 = i & 15;
        float4 e = W4[(2 * kp) * 16 + c4];
        float4 o = W4[(2 * kp + 1) * 16 + c4];
        Bp[kp * 64 + c4 * 4 + 0] = pk2(e.x, o.x);
        Bp[kp * 64 + c4 * 4 + 1] = pk2(e.y, o.y);
        Bp[kp * 64 + c4 * 4 + 2] = pk2(e.z, o.z);
        Bp[kp * 64 + c4 * 4 + 3] = pk2(e.w, o.w);
    }
    if (t < 64) s_aux[t] = is_dst ? out_b[t] : g_tk[t];
    __syncthreads();
    int tile = is_dst ? blockIdx.x - nb : blockIdx.x;
    int row0 = tile * 64;
    int tx = t & 7, ty = t >> 3;             // ty 0..31 -> 2 rows each
    int r0 = row0 + ty * 2;
    const float* feat = is_dst ? feat_dst : feat_src;
    int ra = (r0 < n_rows) ? r0 : n_rows - 1;
    int rb = (r0 + 1 < n_rows) ? r0 + 1 : n_rows - 1;
    const ulonglong2* rpa = (const ulonglong2*)(feat + (size_t)ra * INC);
    const ulonglong2* rpb = (const ulonglong2*)(feat + (size_t)rb * INC);
    int cA = tx * 4, cB = 32 + tx * 4;
    ull acc[2][8];
    #pragma unroll
    for (int i = 0; i < 2; i++)
        #pragma unroll
        for (int c = 0; c < 8; c++) acc[i][c] = 0ULL;
    for (int q = 0; q < 32; q++) {           // each q = 2 k-pairs (4 k's)
        ulonglong2 a0 = __ldg(&rpa[q]);
        ulonglong2 a1 = __ldg(&rpb[q]);
        #pragma unroll
        for (int j = 0; j < 2; j++) {
            int kp = 2 * q + j;
            ull aa0 = j ? a0.y : a0.x;
            ull aa1 = j ? a1.y : a1.x;
            ulonglong2 b0 = *(const ulonglong2*)&Bp[kp * 64 + cA];
            ulonglong2 b1 = *(const ulonglong2*)&Bp[kp * 64 + cA + 2];
            ulonglong2 b2 = *(const ulonglong2*)&Bp[kp * 64 + cB];
            ulonglong2 b3 = *(const ulonglong2*)&Bp[kp * 64 + cB + 2];
            fma2(acc[0][0], aa0, b0.x); fma2(acc[0][1], aa0, b0.y);
            fma2(acc[0][2], aa0, b1.x); fma2(acc[0][3], aa0, b1.y);
            fma2(acc[0][4], aa0, b2.x); fma2(acc[0][5], aa0, b2.y);
            fma2(acc[0][6], aa0, b3.x); fma2(acc[0][7], aa0, b3.y);
            fma2(acc[1][0], aa1, b0.x); fma2(acc[1][1], aa1, b0.y);
            fma2(acc[1][2], aa1, b1.x); fma2(acc[1][3], aa1, b1.y);
            fma2(acc[1][4], aa1, b2.x); fma2(acc[1][5], aa1, b2.y);
            fma2(acc[1][6], aa1, b3.x); fma2(acc[1][7], aa1, b3.y);
        }
    }
    #pragma unroll
    for (int i = 0; i < 2; i++) {
        int r = r0 + i;
        float h[8];
        #pragma unroll
        for (int c = 0; c < 8; c++) h[c] = red2(acc[i][c]);
        if (!is_dst) {
            if (r < n_rows) {
                *(float4*)&g_hsrc[(size_t)r * D + cA] = make_float4(h[0], h[1], h[2], h[3]);
                *(float4*)&g_hsrc[(size_t)r * D + cB] = make_float4(h[4], h[5], h[6], h[7]);
            }
            float ka = h[0] * s_aux[cA] + h[1] * s_aux[cA + 1]
                     + h[2] * s_aux[cA + 2] + h[3] * s_aux[cA + 3]
                     + h[4] * s_aux[cB] + h[5] * s_aux[cB + 1]
                     + h[6] * s_aux[cB + 2] + h[7] * s_aux[cB + 3];
            ka += __shfl_xor_sync(0xffffffffu, ka, 1);
            ka += __shfl_xor_sync(0xffffffffu, ka, 2);
            ka += __shfl_xor_sync(0xffffffffu, ka, 4);
            if (tx == 0 && r < n_rows) g_ka[r] = ka;
        } else if (r < n_rows) {
            *(float4*)&g_outp[(size_t)r * D + cA] = make_float4(
                h[0] + s_aux[cA], h[1] + s_aux[cA + 1],
                h[2] + s_aux[cA + 2], h[3] + s_aux[cA + 3]);
            *(float4*)&g_outp[(size_t)r * D + cB] = make_float4(
                h[4] + s_aux[cB], h[5] + s_aux[cB + 1],
                h[6] + s_aux[cB + 2], h[7] + s_aux[cB + 3]);
        }
    }
}

// ---------------- K_agg: qa + softmax + message sum, ONE pass (warp/node) ---
__global__ void k_agg(const int* __restrict__ src_idx,
                      const float* __restrict__ ew,
                      const float* __restrict__ feat_dst,
                      const float* __restrict__ att_b, int n_nodes) {
    int w = (blockIdx.x * blockDim.x + threadIdx.x) >> 5;
    int lane = threadIdx.x & 31;
    if (w >= n_nodes) return;
    int sl = lane & 15, half = lane >> 4;
    int e0 = g_start[w], e1 = g_start[w + 1];
    if (e0 == e1) {
        if (lane < 16) *(float4*)&g_agg[(size_t)w * D + 4 * sl] =
            make_float4(0.f, 0.f, 0.f, 0.f);
        return;
    }
    float4 f = ((const float4*)(feat_dst + (size_t)w * INC))[lane];
    float4 v = ((const float4*)g_vq)[lane];
    float qa = f.x * v.x + f.y * v.y + f.z * v.z + f.w * v.w;
    #pragma unroll
    for (int o = 16; o > 0; o >>= 1) qa += __shfl_xor_sync(0xffffffffu, qa, o);
    float qn = qa + att_b[0];
    float ce = g_ce;
    float s = 0.f;
    float4 acc = make_float4(0.f, 0.f, 0.f, 0.f);
    for (int e = e0 + half; e < e1; e += 2) {
        int si = src_idx[e];
        float x = qn + g_ka[si] + ew[e] * ce;
        x = (x >= 0.f) ? x : 0.2f * x;
        float al = __expf(x);
        s += al;
        float4 h = *(const float4*)&g_hsrc[(size_t)si * D + 4 * sl];
        acc.x += al * h.x; acc.y += al * h.y; acc.z += al * h.z; acc.w += al * h.w;
    }
    s += __shfl_xor_sync(0xffffffffu, s, 16);
    acc.x += __shfl_xor_sync(0xffffffffu, acc.x, 16);
    acc.y += __shfl_xor_sync(0xffffffffu, acc.y, 16);
    acc.z += __shfl_xor_sync(0xffffffffu, acc.z, 16);
    acc.w += __shfl_xor_sync(0xffffffffu, acc.w, 16);
    float inv = 1.f / (s + 1e-16f);
    if (lane < 16)
        *(float4*)&g_agg[(size_t)w * D + 4 * sl] =
            make_float4(acc.x * inv, acc.y * inv, acc.z * inv, acc.w * inv);
}

// ---------------- K_out: out = g_outp + g_agg @ out_w[64:] (K=64) -----------
#define SMO (32 * 64 * 8)
__global__ void __launch_bounds__(256, 4)
k_out(const float* __restrict__ out_w, float* __restrict__ out, int n_rows) {
    extern __shared__ ull Bp[];              // [32 kp][64 c]
    int t = threadIdx.x;
    const float4* W4 = (const float4*)(out_w + (size_t)D * D);
    for (int i = t; i < 32 * 16; i += 256) {
        int kp = i >> 4, c4 = i & 15;
        float4 e = W4[(2 * kp) * 16 + c4];
        float4 o = W4[(2 * kp + 1) * 16 + c4];
        Bp[kp * 64 + c4 * 4 + 0] = pk2(e.x, o.x);
        Bp[kp * 64 + c4 * 4 + 1] = pk2(e.y, o.y);
        Bp[kp * 64 + c4 * 4 + 2] = pk2(e.z, o.z);
        Bp[kp * 64 + c4 * 4 + 3] = pk2(e.w, o.w);
    }
    __syncthreads();
    int row0 = blockIdx.x * 64;
    int tx = t & 7, ty = t >> 3;
    int r0 = row0 + ty * 2;
    int ra = (r0 < n_rows) ? r0 : n_rows - 1;
    int rb = (r0 + 1 < n_rows) ? r0 + 1 : n_rows - 1;
    const ulonglong2* rpa = (const ulonglong2*)(g_agg + (size_t)ra * D);
    const ulonglong2* rpb = (const ulonglong2*)(g_agg + (size_t)rb * D);
    int cA = tx * 4, cB = 32 + tx * 4;
    ull acc[2][8];
    #pragma unroll
    for (int i = 0; i < 2; i++)
        #pragma unroll
        for (int c = 0; c < 8; c++) acc[i][c] = 0ULL;
    for (int q = 0; q < 16; q++) {
        ulonglong2 a0 = __ldg(&rpa[q]);
        ulonglong2 a1 = __ldg(&rpb[q]);
        #pragma unroll
        for (int j = 0; j < 2; j++) {
            int kp = 2 * q + j;
            ull aa0 = j ? a0.y : a0.x;
            ull aa1 = j ? a1.y : a1.x;
            ulonglong2 b0 = *(const ulonglong2*)&Bp[kp * 64 + cA];
            ulonglong2 b1 = *(const ulonglong2*)&Bp[kp * 64 + cA + 2];
            ulonglong2 b2 = *(const ulonglong2*)&Bp[kp * 64 + cB];
            ulonglong2 b3 = *(const ulonglong2*)&Bp[kp * 64 + cB + 2];
            fma2(acc[0][0], aa0, b0.x); fma2(acc[0][1], aa0, b0.y);
            fma2(acc[0][2], aa0, b1.x); fma2(acc[0][3], aa0, b1.y);
            fma2(acc[0][4], aa0, b2.x); fma2(acc[0][5], aa0, b2.y);
            fma2(acc[0][6], aa0, b3.x); fma2(acc[0][7], aa0, b3.y);
            fma2(acc[1][0], aa1, b0.x); fma2(acc[1][1], aa1, b0.y);
            fma2(acc[1][2], aa1, b1.x); fma2(acc[1][3], aa1, b1.y);
            fma2(acc[1][4], aa1, b2.x); fma2(acc[1][5], aa1, b2.y);
            fma2(acc[1][6], aa1, b3.x); fma2(acc[1][7], aa1, b3.y);
        }
    }
    const ulonglong2* pa[2] = {
        (const ulonglong2*)(g_outp + (size_t)ra * D),
        (const ulonglong2*)(g_outp + (size_t)rb * D) };
    #pragma unroll
    for (int i = 0; i < 2; i++) {
        int r = r0 + i;
        if (r < n_rows) {
            float4 pA = *(const float4*)&g_outp[(size_t)r * D + cA];
            float4 pB = *(const float4*)&g_outp[(size_t)r * D + cB];
            *(float4*)&out[(size_t)r * D + cA] = make_float4(
                pA.x + red2(acc[i][0]), pA.y + red2(acc[i][1]),
                pA.z + red2(acc[i][2]), pA.w + red2(acc[i][3]));
            *(float4*)&out[(size_t)r * D + cB] = make_float4(
                pB.x + red2(acc[i][4]), pB.y + red2(acc[i][5]),
                pB.z + red2(acc[i][6]), pB.w + red2(acc[i][7]));
        }
    }
    (void)pa;
}

// ---------------------------------------------------------------------------
extern "C" void kernel_launch(void* const* d_in, const int* in_sizes, int n_in,
                              void* d_out, int out_size) {
    const float* feat_src    = (const float*)d_in[0];
    const float* feat_dst    = (const float*)d_in[1];
    const float* edge_weight = (const float*)d_in[2];
    const int*   src_idx     = (const int*)d_in[3];
    const int*   dst_idx     = (const int*)d_in[4];
    const float* weight_n    = (const float*)d_in[5];
    const float* weight_e    = (const float*)d_in[6];
    const float* query       = (const float*)d_in[7];
    const float* key_w       = (const float*)d_in[8];
    const float* att_w       = (const float*)d_in[9];
    const float* att_b       = (const float*)d_in[10];
    const float* out_w       = (const float*)d_in[11];
    const float* out_b       = (const float*)d_in[12];
    float* out = (float*)d_out;

    int n_nodes = in_sizes[0] / INC;
    int n_edges = in_sizes[3];
    int nb = (n_nodes + 63) / 64;

    cudaFuncSetAttribute(k_gemm, cudaFuncAttributeMaxDynamicSharedMemorySize, SMG);
    cudaFuncSetAttribute(k_out,  cudaFuncAttributeMaxDynamicSharedMemorySize, SMO);

    int prep_blocks = 33 + (n_edges + 1 + 255) / 256;
    k_prep<<<prep_blocks, 256>>>(weight_n, weight_e, query, key_w, att_w,
                                 out_w, dst_idx, n_nodes, n_edges);
    k_gemm<<<2 * nb, 256, SMG>>>(feat_src, feat_dst, weight_n, out_b,
                                 n_nodes, nb);
    k_agg<<<(n_nodes * 32 + 255) / 256, 256>>>(src_idx, edge_weight, feat_dst,
                                               att_b, n_nodes);
    k_out<<<nb, 256, SMO>>>(out_w, out, n_nodes);
}

// round 13
// speedup vs baseline: 1.3700x; 1.3700x over previous
#include <cuda_runtime.h>
#include <math.h>
#include <cstdint>

#define NN 50000
#define NE 800000
#define INC 128
#define D 64

typedef unsigned long long ull;

// ---------------- scratch (static device globals; no allocation) ------------
__device__ float g_vq[INC];          // weight_n @ (query @ att_w[:d])
__device__ float g_tk[D];            // key_w @ att_w[d:2d]
__device__ float g_ce;               // weight_e[0,:] . att_w[2d:]
__device__ float g_W1[INC * D];      // weight_n @ out_w[:d]
__device__ float g_hsrc[(size_t)NN * D];
__device__ float g_ka[NN];
__device__ float g_agg[(size_t)NN * D];
__device__ float g_outp[(size_t)NN * D];  // feat_dst @ W1 + bias
__device__ int   g_start[NN + 1];

// ---------------- packed f32x2 helpers (Blackwell FFMA2) --------------------
__device__ __forceinline__ ull pk2(float lo, float hi) {
    ull r;
    asm("mov.b64 %0, {%1, %2};" : "=l"(r) : "f"(lo), "f"(hi));
    return r;
}
__device__ __forceinline__ void fma2(ull& d, ull a, ull b) {
    asm("fma.rn.f32x2 %0, %1, %2, %0;" : "+l"(d) : "l"(a), "l"(b));
}
__device__ __forceinline__ float red2(ull v) {   // lo + hi
    float lo, hi;
    asm("mov.b64 {%0, %1}, %2;" : "=f"(lo), "=f"(hi) : "l"(v));
    return lo + hi;
}

// ---------------- K_prep: fold small mats + segment bounds (one launch) -----
__global__ void k_prep(const float* __restrict__ wn,
                       const float* __restrict__ we,
                       const float* __restrict__ query,
                       const float* __restrict__ key_w,
                       const float* __restrict__ att_w,
                       const float* __restrict__ out_w,
                       const int* __restrict__ dst,
                       int n_nodes, int n_edges) {
    int t = threadIdx.x;
    if (blockIdx.x < 32) {
        int idx = blockIdx.x * 256 + t;      // 8192 outputs of W1
        int k = idx >> 6, c = idx & 63;
        float s = 0.f;
        #pragma unroll 8
        for (int j = 0; j < D; j++) s += wn[k * D + j] * out_w[j * D + c];
        g_W1[idx] = s;
        return;
    }
    if (blockIdx.x > 32) {
        int e = (blockIdx.x - 33) * 256 + t;
        if (e > n_edges) return;
        int d1 = (e < n_edges) ? dst[e] : n_nodes;
        int d0 = (e > 0) ? dst[e - 1] : -1;
        for (int n = d0 + 1; n <= d1; n++) g_start[n] = e;
        return;
    }
    __shared__ float s_aw[3 * D];
    __shared__ float s_tq[D];
    for (int i = t; i < 3 * D; i += 256) s_aw[i] = att_w[i];
    __syncthreads();
    if (t < D) {
        float sq = 0.f, sk = 0.f;
        #pragma unroll 8
        for (int j = 0; j < D; j++) {
            sq += query[t * D + j] * s_aw[j];
            sk += key_w[t * D + j] * s_aw[D + j];
        }
        s_tq[t] = sq;
        g_tk[t] = sk;
    }
    if (t == 64) {
        float c = 0.f;
        for (int j = 0; j < D; j++) c += we[j] * s_aw[2 * D + j];
        g_ce = c;
    }
    __syncthreads();
    if (t < INC) {
        float vq = 0.f;
        #pragma unroll 8
        for (int i = 0; i < D; i++) vq += wn[t * D + i] * s_tq[i];
        g_vq[t] = vq;
    }
}

// ---------------- K_gemm: fused K=128 GEMMs, k-pair f32x2 packing -----------
// blocks [0,nb):   g_hsrc = feat_src @ wn  (+ g_ka epilogue with tk)
// blocks [nb,2nb): g_outp = feat_dst @ W1 + out_b
// 64-row tiles, 256 threads, 2 rows x 8 cols per thread.
// Bp[kp][c] = (W[2kp][c], W[2kp+1][c]); A operand = raw ull from LDG.128
// (adjacent k's). Thread columns: c = 2*tx + 16*g  (g=0..3) -> every B load
// is 8 lanes x 16B contiguous = conflict-free LDS.128.
#define SMG (64 * 64 * 8 + 256)
__global__ void __launch_bounds__(256, 3)
k_gemm(const float* __restrict__ feat_src, const float* __restrict__ feat_dst,
       const float* __restrict__ wn, const float* __restrict__ out_b,
       int n_rows, int nb) {
    extern __shared__ ull Bp[];              // [64 kp][64 c]
    float* s_aux = (float*)(Bp + 64 * 64);
    int t = threadIdx.x;
    bool is_dst = blockIdx.x >= nb;
    const float4* W4 = (const float4*)(is_dst ? g_W1 : wn);
    for (int i = t; i < 64 * 16; i += 256) {
        int kp = i >> 4, c4 = i & 15;
        float4 e = W4[(2 * kp) * 16 + c4];
        float4 o = W4[(2 * kp + 1) * 16 + c4];
        Bp[kp * 64 + c4 * 4 + 0] = pk2(e.x, o.x);
        Bp[kp * 64 + c4 * 4 + 1] = pk2(e.y, o.y);
        Bp[kp * 64 + c4 * 4 + 2] = pk2(e.z, o.z);
        Bp[kp * 64 + c4 * 4 + 3] = pk2(e.w, o.w);
    }
    if (t < 64) s_aux[t] = is_dst ? out_b[t] : g_tk[t];
    __syncthreads();
    int tile = is_dst ? blockIdx.x - nb : blockIdx.x;
    int row0 = tile * 64;
    int tx = t & 7, ty = t >> 3;             // ty 0..31 -> 2 rows each
    int r0 = row0 + ty * 2;
    const float* feat = is_dst ? feat_dst : feat_src;
    int ra = (r0 < n_rows) ? r0 : n_rows - 1;
    int rb = (r0 + 1 < n_rows) ? r0 + 1 : n_rows - 1;
    const ulonglong2* rpa = (const ulonglong2*)(feat + (size_t)ra * INC);
    const ulonglong2* rpb = (const ulonglong2*)(feat + (size_t)rb * INC);
    int c0 = 2 * tx;                         // cols: c0 + 16*g, c0 + 16*g + 1
    ull acc[2][8];
    #pragma unroll
    for (int i = 0; i < 2; i++)
        #pragma unroll
        for (int c = 0; c < 8; c++) acc[i][c] = 0ULL;
    for (int q = 0; q < 32; q++) {           // each q = 2 k-pairs (4 k's)
        ulonglong2 a0 = __ldg(&rpa[q]);
        ulonglong2 a1 = __ldg(&rpb[q]);
        #pragma unroll
        for (int j = 0; j < 2; j++) {
            int kp = 2 * q + j;
            ull aa0 = j ? a0.y : a0.x;
            ull aa1 = j ? a1.y : a1.x;
            #pragma unroll
            for (int g = 0; g < 4; g++) {
                ulonglong2 b = *(const ulonglong2*)&Bp[kp * 64 + c0 + 16 * g];
                fma2(acc[0][2 * g],     aa0, b.x);
                fma2(acc[0][2 * g + 1], aa0, b.y);
                fma2(acc[1][2 * g],     aa1, b.x);
                fma2(acc[1][2 * g + 1], aa1, b.y);
            }
        }
    }
    #pragma unroll
    for (int i = 0; i < 2; i++) {
        int r = r0 + i;
        float h[8];
        #pragma unroll
        for (int c = 0; c < 8; c++) h[c] = red2(acc[i][c]);
        if (!is_dst) {
            if (r < n_rows) {
                #pragma unroll
                for (int g = 0; g < 4; g++)
                    *(float2*)&g_hsrc[(size_t)r * D + c0 + 16 * g] =
                        make_float2(h[2 * g], h[2 * g + 1]);
            }
            float ka = 0.f;
            #pragma unroll
            for (int g = 0; g < 4; g++)
                ka += h[2 * g] * s_aux[c0 + 16 * g]
                    + h[2 * g + 1] * s_aux[c0 + 16 * g + 1];
            ka += __shfl_xor_sync(0xffffffffu, ka, 1);
            ka += __shfl_xor_sync(0xffffffffu, ka, 2);
            ka += __shfl_xor_sync(0xffffffffu, ka, 4);
            if (tx == 0 && r < n_rows) g_ka[r] = ka;
        } else if (r < n_rows) {
            #pragma unroll
            for (int g = 0; g < 4; g++)
                *(float2*)&g_outp[(size_t)r * D + c0 + 16 * g] =
                    make_float2(h[2 * g] + s_aux[c0 + 16 * g],
                                h[2 * g + 1] + s_aux[c0 + 16 * g + 1]);
        }
    }
}

// ---------------- K_agg: qa + softmax + message sum, ONE pass (warp/node) ---
__global__ void k_agg(const int* __restrict__ src_idx,
                      const float* __restrict__ ew,
                      const float* __restrict__ feat_dst,
                      const float* __restrict__ att_b, int n_nodes) {
    int w = (blockIdx.x * blockDim.x + threadIdx.x) >> 5;
    int lane = threadIdx.x & 31;
    if (w >= n_nodes) return;
    int sl = lane & 15, half = lane >> 4;
    int e0 = g_start[w], e1 = g_start[w + 1];
    if (e0 == e1) {
        if (lane < 16) *(float4*)&g_agg[(size_t)w * D + 4 * sl] =
            make_float4(0.f, 0.f, 0.f, 0.f);
        return;
    }
    float4 f = ((const float4*)(feat_dst + (size_t)w * INC))[lane];
    float4 v = ((const float4*)g_vq)[lane];
    float qa = f.x * v.x + f.y * v.y + f.z * v.z + f.w * v.w;
    #pragma unroll
    for (int o = 16; o > 0; o >>= 1) qa += __shfl_xor_sync(0xffffffffu, qa, o);
    float qn = qa + att_b[0];
    float ce = g_ce;
    float s = 0.f;
    float4 acc = make_float4(0.f, 0.f, 0.f, 0.f);
    for (int e = e0 + half; e < e1; e += 2) {
        int si = src_idx[e];
        float x = qn + g_ka[si] + ew[e] * ce;
        x = (x >= 0.f) ? x : 0.2f * x;
        float al = __expf(x);
        s += al;
        float4 h = *(const float4*)&g_hsrc[(size_t)si * D + 4 * sl];
        acc.x += al * h.x; acc.y += al * h.y; acc.z += al * h.z; acc.w += al * h.w;
    }
    s += __shfl_xor_sync(0xffffffffu, s, 16);
    acc.x += __shfl_xor_sync(0xffffffffu, acc.x, 16);
    acc.y += __shfl_xor_sync(0xffffffffu, acc.y, 16);
    acc.z += __shfl_xor_sync(0xffffffffu, acc.z, 16);
    acc.w += __shfl_xor_sync(0xffffffffu, acc.w, 16);
    float inv = 1.f / (s + 1e-16f);
    if (lane < 16)
        *(float4*)&g_agg[(size_t)w * D + 4 * sl] =
            make_float4(acc.x * inv, acc.y * inv, acc.z * inv, acc.w * inv);
}

// ---------------- K_out: out = g_outp + g_agg @ out_w[64:] (K=64) -----------
#define SMO (32 * 64 * 8)
__global__ void __launch_bounds__(256, 3)
k_out(const float* __restrict__ out_w, float* __restrict__ out, int n_rows) {
    extern __shared__ ull Bp[];              // [32 kp][64 c]
    int t = threadIdx.x;
    const float4* W4 = (const float4*)(out_w + (size_t)D * D);
    for (int i = t; i < 32 * 16; i += 256) {
        int kp = i >> 4, c4 = i & 15;
        float4 e = W4[(2 * kp) * 16 + c4];
        float4 o = W4[(2 * kp + 1) * 16 + c4];
        Bp[kp * 64 + c4 * 4 + 0] = pk2(e.x, o.x);
        Bp[kp * 64 + c4 * 4 + 1] = pk2(e.y, o.y);
        Bp[kp * 64 + c4 * 4 + 2] = pk2(e.z, o.z);
        Bp[kp * 64 + c4 * 4 + 3] = pk2(e.w, o.w);
    }
    __syncthreads();
    int row0 = blockIdx.x * 64;
    int tx = t & 7, ty = t >> 3;
    int r0 = row0 + ty * 2;
    int ra = (r0 < n_rows) ? r0 : n_rows - 1;
    int rb = (r0 + 1 < n_rows) ? r0 + 1 : n_rows - 1;
    const ulonglong2* rpa = (const ulonglong2*)(g_agg + (size_t)ra * D);
    const ulonglong2* rpb = (const ulonglong2*)(g_agg + (size_t)rb * D);
    int c0 = 2 * tx;
    ull acc[2][8];
    #pragma unroll
    for (int i = 0; i < 2; i++)
        #pragma unroll
        for (int c = 0; c < 8; c++) acc[i][c] = 0ULL;
    for (int q = 0; q < 16; q++) {
        ulonglong2 a0 = __ldg(&rpa[q]);
        ulonglong2 a1 = __ldg(&rpb[q]);
        #pragma unroll
        for (int j = 0; j < 2; j++) {
            int kp = 2 * q + j;
            ull aa0 = j ? a0.y : a0.x;
            ull aa1 = j ? a1.y : a1.x;
            #pragma unroll
            for (int g = 0; g < 4; g++) {
                ulonglong2 b = *(const ulonglong2*)&Bp[kp * 64 + c0 + 16 * g];
                fma2(acc[0][2 * g],     aa0, b.x);
                fma2(acc[0][2 * g + 1], aa0, b.y);
                fma2(acc[1][2 * g],     aa1, b.x);
                fma2(acc[1][2 * g + 1], aa1, b.y);
            }
        }
    }
    #pragma unroll
    for (int i = 0; i < 2; i++) {
        int r = r0 + i;
        if (r < n_rows) {
            #pragma unroll
            for (int g = 0; g < 4; g++) {
                int c = c0 + 16 * g;
                float2 p = *(const float2*)&g_outp[(size_t)r * D + c];
                *(float2*)&out[(size_t)r * D + c] = make_float2(
                    p.x + red2(acc[i][2 * g]),
                    p.y + red2(acc[i][2 * g + 1]));
            }
        }
    }
}

// ---------------------------------------------------------------------------
extern "C" void kernel_launch(void* const* d_in, const int* in_sizes, int n_in,
                              void* d_out, int out_size) {
    const float* feat_src    = (const float*)d_in[0];
    const float* feat_dst    = (const float*)d_in[1];
    const float* edge_weight = (const float*)d_in[2];
    const int*   src_idx     = (const int*)d_in[3];
    const int*   dst_idx     = (const int*)d_in[4];
    const float* weight_n    = (const float*)d_in[5];
    const float* weight_e    = (const float*)d_in[6];
    const float* query       = (const float*)d_in[7];
    const float* key_w       = (const float*)d_in[8];
    const float* att_w       = (const float*)d_in[9];
    const float* att_b       = (const float*)d_in[10];
    const float* out_w       = (const float*)d_in[11];
    const float* out_b       = (const float*)d_in[12];
    float* out = (float*)d_out;

    int n_nodes = in_sizes[0] / INC;
    int n_edges = in_sizes[3];
    int nb = (n_nodes + 63) / 64;

    cudaFuncSetAttribute(k_gemm, cudaFuncAttributeMaxDynamicSharedMemorySize, SMG);
    cudaFuncSetAttribute(k_out,  cudaFuncAttributeMaxDynamicSharedMemorySize, SMO);

    int prep_blocks = 33 + (n_edges + 1 + 255) / 256;
    k_prep<<<prep_blocks, 256>>>(weight_n, weight_e, query, key_w, att_w,
                                 out_w, dst_idx, n_nodes, n_edges);
    k_gemm<<<2 * nb, 256, SMG>>>(feat_src, feat_dst, weight_n, out_b,
                                 n_nodes, nb);
    k_agg<<<(n_nodes * 32 + 255) / 256, 256>>>(src_idx, edge_weight, feat_dst,
                                               att_b, n_nodes);
    k_out<<<nb, 256, SMO>>>(out_w, out, n_nodes);
}

// round 14
// speedup vs baseline: 1.3867x; 1.0122x over previous
#include <cuda_runtime.h>
#include <math.h>
#include <cstdint>

#define NN 50000
#define NE 800000
#define INC 128
#define D 64

typedef unsigned long long ull;

// ---------------- scratch (static device globals; no allocation) ------------
__device__ float g_vq[INC];          // weight_n @ (query @ att_w[:d])
__device__ float g_tk[D];            // key_w @ att_w[d:2d]
__device__ float g_ce;               // weight_e[0,:] . att_w[2d:]
__device__ float g_W1[INC * D];      // weight_n @ out_w[:d]
__device__ float g_hsrc[(size_t)NN * D];
__device__ float g_ka[NN];
__device__ float g_agg[(size_t)NN * D];
__device__ int   g_start[NN + 1];

// ---------------- packed f32x2 helpers (Blackwell FFMA2) --------------------
__device__ __forceinline__ ull pk2(float lo, float hi) {
    ull r;
    asm("mov.b64 %0, {%1, %2};" : "=l"(r) : "f"(lo), "f"(hi));
    return r;
}
__device__ __forceinline__ void fma2(ull& d, ull a, ull b) {
    asm("fma.rn.f32x2 %0, %1, %2, %0;" : "+l"(d) : "l"(a), "l"(b));
}
__device__ __forceinline__ float2 up2(ull v) {
    float lo, hi;
    asm("mov.b64 {%0, %1}, %2;" : "=f"(lo), "=f"(hi) : "l"(v));
    return make_float2(lo, hi);
}

// ---------------- K_prep: fold small mats + segment bounds (one launch) -----
__global__ void k_prep(const float* __restrict__ wn,
                       const float* __restrict__ we,
                       const float* __restrict__ query,
                       const float* __restrict__ key_w,
                       const float* __restrict__ att_w,
                       const float* __restrict__ out_w,
                       const int* __restrict__ dst,
                       int n_nodes, int n_edges) {
    int t = threadIdx.x;
    if (blockIdx.x < 32) {
        int idx = blockIdx.x * 256 + t;      // 8192 outputs of W1
        int k = idx >> 6, c = idx & 63;
        float s = 0.f;
        #pragma unroll 8
        for (int j = 0; j < D; j++) s += wn[k * D + j] * out_w[j * D + c];
        g_W1[idx] = s;
        return;
    }
    if (blockIdx.x > 32) {
        int e = (blockIdx.x - 33) * 256 + t;
        if (e > n_edges) return;
        int d1 = (e < n_edges) ? dst[e] : n_nodes;
        int d0 = (e > 0) ? dst[e - 1] : -1;
        for (int n = d0 + 1; n <= d1; n++) g_start[n] = e;
        return;
    }
    __shared__ float s_aw[3 * D];
    __shared__ float s_tq[D];
    for (int i = t; i < 3 * D; i += 256) s_aw[i] = att_w[i];
    __syncthreads();
    if (t < D) {
        float sq = 0.f, sk = 0.f;
        #pragma unroll 8
        for (int j = 0; j < D; j++) {
            sq += query[t * D + j] * s_aw[j];
            sk += key_w[t * D + j] * s_aw[D + j];
        }
        s_tq[t] = sq;
        g_tk[t] = sk;
    }
    if (t == 64) {
        float c = 0.f;
        for (int j = 0; j < D; j++) c += we[j] * s_aw[2 * D + j];
        g_ce = c;
    }
    __syncthreads();
    if (t < INC) {
        float vq = 0.f;
        #pragma unroll 8
        for (int i = 0; i < D; i++) vq += wn[t * D + i] * s_tq[i];
        g_vq[t] = vq;
    }
}

// ---------------- K_mm1: h_src = feat_src @ W_n  (+ ka epilogue) ------------
// 64 rows/block, 256 threads, 2x8 micro-tile (low regs -> 4 CTAs/SM).
// A via LDG.128 broadcast, B pre-packed column-pair f32x2 in smem (R10 layout).
#define SMW1 (INC * 32 * 8)          // 32 KB of packed pairs
__global__ void __launch_bounds__(256, 4)
k_mm1(const float* __restrict__ feat, const float* __restrict__ wn, int n_rows) {
    extern __shared__ ull Ws2[];     // [k][32 pairs]
    int t = threadIdx.x;
    const float4* wn4 = (const float4*)wn;
    for (int i = t; i < INC * 16; i += 256) {
        float4 v = wn4[i];
        int k = i >> 4, c4 = i & 15;
        Ws2[k * 32 + c4 * 2]     = pk2(v.x, v.y);
        Ws2[k * 32 + c4 * 2 + 1] = pk2(v.z, v.w);
    }
    __syncthreads();
    int row0 = blockIdx.x * 64;
    int tx = t & 7, ty = t >> 3;     // ty 0..31 -> 2 rows
    int r0 = row0 + ty * 2;
    int ra = (r0 < n_rows) ? r0 : n_rows - 1;
    int rb = (r0 + 1 < n_rows) ? r0 + 1 : n_rows - 1;
    const float4* rpa = (const float4*)(feat + (size_t)ra * INC);
    const float4* rpb = (const float4*)(feat + (size_t)rb * INC);
    int cA = tx * 4, cB = 32 + tx * 4;
    ull acc[2][4];
    #pragma unroll
    for (int i = 0; i < 2; i++)
        #pragma unroll
        for (int c = 0; c < 4; c++) acc[i][c] = 0ULL;
    for (int kk = 0; kk < 32; kk++) {
        float4 a0 = __ldg(&rpa[kk]);
        float4 a1 = __ldg(&rpb[kk]);
        #pragma unroll
        for (int j = 0; j < 4; j++) {
            int k = kk * 4 + j;
            ulonglong2 bA = *(const ulonglong2*)&Ws2[k * 32 + tx * 2];
            ulonglong2 bB = *(const ulonglong2*)&Ws2[k * 32 + 16 + tx * 2];
            float s0 = (j == 0) ? a0.x : (j == 1) ? a0.y : (j == 2) ? a0.z : a0.w;
            float s1 = (j == 0) ? a1.x : (j == 1) ? a1.y : (j == 2) ? a1.z : a1.w;
            ull aa0 = pk2(s0, s0), aa1 = pk2(s1, s1);
            fma2(acc[0][0], aa0, bA.x); fma2(acc[0][1], aa0, bA.y);
            fma2(acc[0][2], aa0, bB.x); fma2(acc[0][3], aa0, bB.y);
            fma2(acc[1][0], aa1, bA.x); fma2(acc[1][1], aa1, bA.y);
            fma2(acc[1][2], aa1, bB.x); fma2(acc[1][3], aa1, bB.y);
        }
    }
    float tkA[4], tkB[4];
    #pragma unroll
    for (int j = 0; j < 4; j++) { tkA[j] = g_tk[cA + j]; tkB[j] = g_tk[cB + j]; }
    #pragma unroll
    for (int i = 0; i < 2; i++) {
        int r = r0 + i;
        float2 p0 = up2(acc[i][0]), p1 = up2(acc[i][1]);
        float2 p2 = up2(acc[i][2]), p3 = up2(acc[i][3]);
        if (r < n_rows) {
            *(float4*)&g_hsrc[(size_t)r * D + cA] = make_float4(p0.x, p0.y, p1.x, p1.y);
            *(float4*)&g_hsrc[(size_t)r * D + cB] = make_float4(p2.x, p2.y, p3.x, p3.y);
        }
        float ka = p0.x * tkA[0] + p0.y * tkA[1] + p1.x * tkA[2] + p1.y * tkA[3]
                 + p2.x * tkB[0] + p2.y * tkB[1] + p3.x * tkB[2] + p3.y * tkB[3];
        ka += __shfl_xor_sync(0xffffffffu, ka, 1);
        ka += __shfl_xor_sync(0xffffffffu, ka, 2);
        ka += __shfl_xor_sync(0xffffffffu, ka, 4);
        if (tx == 0 && r < n_rows) g_ka[r] = ka;
    }
}

// ---------------- K_agg: qa + softmax + message sum, ONE pass (warp/node) ---
__global__ void k_agg(const int* __restrict__ src_idx,
                      const float* __restrict__ ew,
                      const float* __restrict__ feat_dst,
                      const float* __restrict__ att_b, int n_nodes) {
    int w = (blockIdx.x * blockDim.x + threadIdx.x) >> 5;
    int lane = threadIdx.x & 31;
    if (w >= n_nodes) return;
    int sl = lane & 15, half = lane >> 4;
    int e0 = g_start[w], e1 = g_start[w + 1];
    if (e0 == e1) {
        if (lane < 16) *(float4*)&g_agg[(size_t)w * D + 4 * sl] =
            make_float4(0.f, 0.f, 0.f, 0.f);
        return;
    }
    float4 f = ((const float4*)(feat_dst + (size_t)w * INC))[lane];
    float4 v = ((const float4*)g_vq)[lane];
    float qa = f.x * v.x + f.y * v.y + f.z * v.z + f.w * v.w;
    #pragma unroll
    for (int o = 16; o > 0; o >>= 1) qa += __shfl_xor_sync(0xffffffffu, qa, o);
    float qn = qa + att_b[0];
    float ce = g_ce;
    float s = 0.f;
    float4 acc = make_float4(0.f, 0.f, 0.f, 0.f);
    for (int e = e0 + half; e < e1; e += 2) {
        int si = src_idx[e];
        float x = qn + g_ka[si] + ew[e] * ce;
        x = (x >= 0.f) ? x : 0.2f * x;
        float al = __expf(x);
        s += al;
        float4 h = *(const float4*)&g_hsrc[(size_t)si * D + 4 * sl];
        acc.x += al * h.x; acc.y += al * h.y; acc.z += al * h.z; acc.w += al * h.w;
    }
    s += __shfl_xor_sync(0xffffffffu, s, 16);
    acc.x += __shfl_xor_sync(0xffffffffu, acc.x, 16);
    acc.y += __shfl_xor_sync(0xffffffffu, acc.y, 16);
    acc.z += __shfl_xor_sync(0xffffffffu, acc.z, 16);
    acc.w += __shfl_xor_sync(0xffffffffu, acc.w, 16);
    float inv = 1.f / (s + 1e-16f);
    if (lane < 16)
        *(float4*)&g_agg[(size_t)w * D + 4 * sl] =
            make_float4(acc.x * inv, acc.y * inv, acc.z * inv, acc.w * inv);
}

// ---------------- K_mm2: out = feat_dst@W1 + agg@out_w[64:] + b (K=192) -----
// 64 rows/block, 2x8 micro-tile, two sequential K phases
#define KK2 (INC + D)
#define SMW2 (KK2 * 32 * 8)          // 48 KB
__global__ void __launch_bounds__(256, 4)
k_mm2(const float* __restrict__ feat_dst, const float* __restrict__ out_w,
      const float* __restrict__ out_b, float* __restrict__ out, int n_rows) {
    extern __shared__ ull Ws2[];     // [k][32 pairs], k<192
    int t = threadIdx.x;
    const float4* w14 = (const float4*)g_W1;
    for (int i = t; i < INC * 16; i += 256) {
        float4 v = w14[i];
        int k = i >> 4, c4 = i & 15;
        Ws2[k * 32 + c4 * 2]     = pk2(v.x, v.y);
        Ws2[k * 32 + c4 * 2 + 1] = pk2(v.z, v.w);
    }
    const float4* ow4 = (const float4*)(out_w + (size_t)D * D);
    for (int i = t; i < D * 16; i += 256) {
        float4 v = ow4[i];
        int k = INC + (i >> 4), c4 = i & 15;
        Ws2[k * 32 + c4 * 2]     = pk2(v.x, v.y);
        Ws2[k * 32 + c4 * 2 + 1] = pk2(v.z, v.w);
    }
    __syncthreads();
    int row0 = blockIdx.x * 64;
    int tx = t & 7, ty = t >> 3;
    int r0 = row0 + ty * 2;
    int ra = (r0 < n_rows) ? r0 : n_rows - 1;
    int rb = (r0 + 1 < n_rows) ? r0 + 1 : n_rows - 1;
    int cA = tx * 4, cB = 32 + tx * 4;
    float4 obA = *(const float4*)&out_b[cA];
    float4 obB = *(const float4*)&out_b[cB];
    ull acc[2][4];
    #pragma unroll
    for (int i = 0; i < 2; i++) {
        acc[i][0] = pk2(obA.x, obA.y); acc[i][1] = pk2(obA.z, obA.w);
        acc[i][2] = pk2(obB.x, obB.y); acc[i][3] = pk2(obB.z, obB.w);
    }
    // phase 1: feat_dst, K = 0..127
    {
        const float4* rpa = (const float4*)(feat_dst + (size_t)ra * INC);
        const float4* rpb = (const float4*)(feat_dst + (size_t)rb * INC);
        for (int kk = 0; kk < 32; kk++) {
            float4 a0 = __ldg(&rpa[kk]);
            float4 a1 = __ldg(&rpb[kk]);
            #pragma unroll
            for (int j = 0; j < 4; j++) {
                int k = kk * 4 + j;
                ulonglong2 bA = *(const ulonglong2*)&Ws2[k * 32 + tx * 2];
                ulonglong2 bB = *(const ulonglong2*)&Ws2[k * 32 + 16 + tx * 2];
                float s0 = (j == 0) ? a0.x : (j == 1) ? a0.y : (j == 2) ? a0.z : a0.w;
                float s1 = (j == 0) ? a1.x : (j == 1) ? a1.y : (j == 2) ? a1.z : a1.w;
                ull aa0 = pk2(s0, s0), aa1 = pk2(s1, s1);
                fma2(acc[0][0], aa0, bA.x); fma2(acc[0][1], aa0, bA.y);
                fma2(acc[0][2], aa0, bB.x); fma2(acc[0][3], aa0, bB.y);
                fma2(acc[1][0], aa1, bA.x); fma2(acc[1][1], aa1, bA.y);
                fma2(acc[1][2], aa1, bB.x); fma2(acc[1][3], aa1, bB.y);
            }
        }
    }
    // phase 2: agg, K = 128..191
    {
        const float4* apa = (const float4*)(g_agg + (size_t)ra * D);
        const float4* apb = (const float4*)(g_agg + (size_t)rb * D);
        for (int kk = 0; kk < 16; kk++) {
            float4 a0 = __ldg(&apa[kk]);
            float4 a1 = __ldg(&apb[kk]);
            #pragma unroll
            for (int j = 0; j < 4; j++) {
                int k = INC + kk * 4 + j;
                ulonglong2 bA = *(const ulonglong2*)&Ws2[k * 32 + tx * 2];
                ulonglong2 bB = *(const ulonglong2*)&Ws2[k * 32 + 16 + tx * 2];
                float s0 = (j == 0) ? a0.x : (j == 1) ? a0.y : (j == 2) ? a0.z : a0.w;
                float s1 = (j == 0) ? a1.x : (j == 1) ? a1.y : (j == 2) ? a1.z : a1.w;
                ull aa0 = pk2(s0, s0), aa1 = pk2(s1, s1);
                fma2(acc[0][0], aa0, bA.x); fma2(acc[0][1], aa0, bA.y);
                fma2(acc[0][2], aa0, bB.x); fma2(acc[0][3], aa0, bB.y);
                fma2(acc[1][0], aa1, bA.x); fma2(acc[1][1], aa1, bA.y);
                fma2(acc[1][2], aa1, bB.x); fma2(acc[1][3], aa1, bB.y);
            }
        }
    }
    #pragma unroll
    for (int i = 0; i < 2; i++) {
        int r = r0 + i;
        if (r < n_rows) {
            float2 p0 = up2(acc[i][0]), p1 = up2(acc[i][1]);
            float2 p2 = up2(acc[i][2]), p3 = up2(acc[i][3]);
            *(float4*)&out[(size_t)r * D + cA] = make_float4(p0.x, p0.y, p1.x, p1.y);
            *(float4*)&out[(size_t)r * D + cB] = make_float4(p2.x, p2.y, p3.x, p3.y);
        }
    }
}

// ---------------------------------------------------------------------------
extern "C" void kernel_launch(void* const* d_in, const int* in_sizes, int n_in,
                              void* d_out, int out_size) {
    const float* feat_src    = (const float*)d_in[0];
    const float* feat_dst    = (const float*)d_in[1];
    const float* edge_weight = (const float*)d_in[2];
    const int*   src_idx     = (const int*)d_in[3];
    const int*   dst_idx     = (const int*)d_in[4];
    const float* weight_n    = (const float*)d_in[5];
    const float* weight_e    = (const float*)d_in[6];
    const float* query       = (const float*)d_in[7];
    const float* key_w       = (const float*)d_in[8];
    const float* att_w       = (const float*)d_in[9];
    const float* att_b       = (const float*)d_in[10];
    const float* out_w       = (const float*)d_in[11];
    const float* out_b       = (const float*)d_in[12];
    float* out = (float*)d_out;

    int n_nodes = in_sizes[0] / INC;
    int n_edges = in_sizes[3];
    int nb = (n_nodes + 63) / 64;

    cudaFuncSetAttribute(k_mm1, cudaFuncAttributeMaxDynamicSharedMemorySize, SMW1);
    cudaFuncSetAttribute(k_mm2, cudaFuncAttributeMaxDynamicSharedMemorySize, SMW2);

    int prep_blocks = 33 + (n_edges + 1 + 255) / 256;
    k_prep<<<prep_blocks, 256>>>(weight_n, weight_e, query, key_w, att_w,
                                 out_w, dst_idx, n_nodes, n_edges);
    k_mm1<<<nb, 256, SMW1>>>(feat_src, weight_n, n_nodes);
    k_agg<<<(n_nodes * 32 + 255) / 256, 256>>>(src_idx, edge_weight, feat_dst,
                                               att_b, n_nodes);
    k_mm2<<<nb, 256, SMW2>>>(feat_dst, out_w, out_b, out, n_nodes);
}

// round 15
// speedup vs baseline: 1.8045x; 1.3012x over previous
#include <cuda_runtime.h>
#include <math.h>
#include <cstdint>

#define NN 50000
#define NE 800000
#define INC 128
#define D 64
#define CH 8                          // k's per pipeline stage
#define STG 4                         // stage buffers

typedef unsigned long long ull;

// ---------------- scratch (static device globals; no allocation) ------------
__device__ float g_vq[INC];
__device__ float g_tk[D];
__device__ float g_ce;
__device__ float g_W1[INC * D];
__device__ float g_hsrc[(size_t)NN * D];
__device__ float g_ka[NN];
__device__ float g_agg[(size_t)NN * D];
__device__ int   g_start[NN + 1];

// ---------------- helpers ----------------------------------------------------
__device__ __forceinline__ ull pk2(float lo, float hi) {
    ull r;
    asm("mov.b64 %0, {%1, %2};" : "=l"(r) : "f"(lo), "f"(hi));
    return r;
}
__device__ __forceinline__ void fma2(ull& d, ull a, ull b) {
    asm("fma.rn.f32x2 %0, %1, %2, %0;" : "+l"(d) : "l"(a), "l"(b));
}
__device__ __forceinline__ float2 up2(ull v) {
    float lo, hi;
    asm("mov.b64 {%0, %1}, %2;" : "=f"(lo), "=f"(hi) : "l"(v));
    return make_float2(lo, hi);
}
__device__ __forceinline__ uint32_t smem_u32(const void* p) {
    uint32_t a;
    asm("{ .reg .u64 t; cvta.to.shared.u64 t, %1; cvt.u32.u64 %0, t; }"
        : "=r"(a) : "l"(p));
    return a;
}
__device__ __forceinline__ void cpa16(uint32_t s, const void* g) {
    asm volatile("cp.async.cg.shared.global [%0], [%1], 16;" :: "r"(s), "l"(g));
}
#define CPA_COMMIT() asm volatile("cp.async.commit_group;" ::: "memory")
#define CPA_WAIT2()  asm volatile("cp.async.wait_group 2;" ::: "memory")

// ---------------- K_prep: fold small mats + segment bounds ------------------
__global__ void k_prep(const float* __restrict__ wn,
                       const float* __restrict__ we,
                       const float* __restrict__ query,
                       const float* __restrict__ key_w,
                       const float* __restrict__ att_w,
                       const float* __restrict__ out_w,
                       const int* __restrict__ dst,
                       int n_nodes, int n_edges) {
    int t = threadIdx.x;
    if (blockIdx.x < 32) {
        int idx = blockIdx.x * 256 + t;
        int k = idx >> 6, c = idx & 63;
        float s = 0.f;
        #pragma unroll 8
        for (int j = 0; j < D; j++) s += wn[k * D + j] * out_w[j * D + c];
        g_W1[idx] = s;
        return;
    }
    if (blockIdx.x > 32) {
        int e = (blockIdx.x - 33) * 256 + t;
        if (e > n_edges) return;
        int d1 = (e < n_edges) ? dst[e] : n_nodes;
        int d0 = (e > 0) ? dst[e - 1] : -1;
        for (int n = d0 + 1; n <= d1; n++) g_start[n] = e;
        return;
    }
    __shared__ float s_aw[3 * D];
    __shared__ float s_tq[D];
    for (int i = t; i < 3 * D; i += 256) s_aw[i] = att_w[i];
    __syncthreads();
    if (t < D) {
        float sq = 0.f, sk = 0.f;
        #pragma unroll 8
        for (int j = 0; j < D; j++) {
            sq += query[t * D + j] * s_aw[j];
            sk += key_w[t * D + j] * s_aw[D + j];
        }
        s_tq[t] = sq;
        g_tk[t] = sk;
    }
    if (t == 64) {
        float c = 0.f;
        for (int j = 0; j < D; j++) c += we[j] * s_aw[2 * D + j];
        g_ce = c;
    }
    __syncthreads();
    if (t < INC) {
        float vq = 0.f;
        #pragma unroll 8
        for (int i = 0; i < D; i++) vq += wn[t * D + i] * s_tq[i];
        g_vq[t] = vq;
    }
}

// ---------------- K_mm1: h_src = feat_src @ W_n  (+ ka epilogue) ------------
// 128-row tiles, 256 threads, 4 rows x 8 cols (rows = ty + 32*i).
// A pipelined via cp.async (4 buffers, 3 deep); B packed column pairs (R10).
#define SMW1 (INC * 32 * 8 + STG * INC * CH * 4)    // 32KB + 16KB
__global__ void __launch_bounds__(256, 3)
k_mm1(const float* __restrict__ feat, const float* __restrict__ wn, int n_rows) {
    extern __shared__ ull Ws2[];                 // [128 k][32 pairs]
    float* As = (float*)(Ws2 + INC * 32);        // [STG][128 row][CH]
    uint32_t as_base = smem_u32(As);
    int t = threadIdx.x;
    const float4* wn4 = (const float4*)wn;
    for (int i = t; i < INC * 16; i += 256) {
        float4 v = wn4[i];
        int k = i >> 4, c4 = i & 15;
        Ws2[k * 32 + c4 * 2]     = pk2(v.x, v.y);
        Ws2[k * 32 + c4 * 2 + 1] = pk2(v.z, v.w);
    }
    int row0 = blockIdx.x * 128;
    int lrow = t >> 1, half = t & 1;             // stage-load: 2 thr/row
    int grow = row0 + lrow; if (grow > n_rows - 1) grow = n_rows - 1;
    const float* gsrc = feat + (size_t)grow * INC + half * 4;
    uint32_t sdst = as_base + (lrow * CH + half * 4) * 4;
    const int NS = INC / CH;                     // 16 stages
    #pragma unroll
    for (int s = 0; s < 3; s++) {                // prologue
        cpa16(sdst + (s % STG) * INC * CH * 4, gsrc + s * CH);
        CPA_COMMIT();
    }
    int tx = t & 7, ty = t >> 3;                 // compute mapping
    int cA = tx * 4, cB = 32 + tx * 4;
    ull acc[4][4];
    #pragma unroll
    for (int i = 0; i < 4; i++)
        #pragma unroll
        for (int c = 0; c < 4; c++) acc[i][c] = 0ULL;
    for (int s = 0; s < NS; s++) {
        CPA_WAIT2();
        __syncthreads();
        if (s + 3 < NS) cpa16(sdst + ((s + 3) % STG) * INC * CH * 4,
                              gsrc + (s + 3) * CH);
        CPA_COMMIT();
        const float* Ast = As + (s % STG) * INC * CH;
        #pragma unroll
        for (int j = 0; j < CH; j++) {
            int k = s * CH + j;
            ulonglong2 bA = *(const ulonglong2*)&Ws2[k * 32 + tx * 2];
            ulonglong2 bB = *(const ulonglong2*)&Ws2[k * 32 + 16 + tx * 2];
            #pragma unroll
            for (int i = 0; i < 4; i++) {
                float a = Ast[(ty + 32 * i) * CH + j];
                ull aa = pk2(a, a);
                fma2(acc[i][0], aa, bA.x); fma2(acc[i][1], aa, bA.y);
                fma2(acc[i][2], aa, bB.x); fma2(acc[i][3], aa, bB.y);
            }
        }
    }
    float tkA[4], tkB[4];
    #pragma unroll
    for (int j = 0; j < 4; j++) { tkA[j] = g_tk[cA + j]; tkB[j] = g_tk[cB + j]; }
    #pragma unroll
    for (int i = 0; i < 4; i++) {
        int r = row0 + ty + 32 * i;
        float2 p0 = up2(acc[i][0]), p1 = up2(acc[i][1]);
        float2 p2 = up2(acc[i][2]), p3 = up2(acc[i][3]);
        if (r < n_rows) {
            *(float4*)&g_hsrc[(size_t)r * D + cA] = make_float4(p0.x, p0.y, p1.x, p1.y);
            *(float4*)&g_hsrc[(size_t)r * D + cB] = make_float4(p2.x, p2.y, p3.x, p3.y);
        }
        float ka = p0.x * tkA[0] + p0.y * tkA[1] + p1.x * tkA[2] + p1.y * tkA[3]
                 + p2.x * tkB[0] + p2.y * tkB[1] + p3.x * tkB[2] + p3.y * tkB[3];
        ka += __shfl_xor_sync(0xffffffffu, ka, 1);
        ka += __shfl_xor_sync(0xffffffffu, ka, 2);
        ka += __shfl_xor_sync(0xffffffffu, ka, 4);
        if (tx == 0 && r < n_rows) g_ka[r] = ka;
    }
}

// ---------------- K_agg: qa + softmax + message sum, ONE pass (warp/node) ---
__global__ void k_agg(const int* __restrict__ src_idx,
                      const float* __restrict__ ew,
                      const float* __restrict__ feat_dst,
                      const float* __restrict__ att_b, int n_nodes) {
    int w = (blockIdx.x * blockDim.x + threadIdx.x) >> 5;
    int lane = threadIdx.x & 31;
    if (w >= n_nodes) return;
    int sl = lane & 15, half = lane >> 4;
    int e0 = g_start[w], e1 = g_start[w + 1];
    if (e0 == e1) {
        if (lane < 16) *(float4*)&g_agg[(size_t)w * D + 4 * sl] =
            make_float4(0.f, 0.f, 0.f, 0.f);
        return;
    }
    float4 f = ((const float4*)(feat_dst + (size_t)w * INC))[lane];
    float4 v = ((const float4*)g_vq)[lane];
    float qa = f.x * v.x + f.y * v.y + f.z * v.z + f.w * v.w;
    #pragma unroll
    for (int o = 16; o > 0; o >>= 1) qa += __shfl_xor_sync(0xffffffffu, qa, o);
    float qn = qa + att_b[0];
    float ce = g_ce;
    float s = 0.f;
    float4 acc = make_float4(0.f, 0.f, 0.f, 0.f);
    for (int e = e0 + half; e < e1; e += 2) {
        int si = src_idx[e];
        float x = qn + g_ka[si] + ew[e] * ce;
        x = (x >= 0.f) ? x : 0.2f * x;
        float al = __expf(x);
        s += al;
        float4 h = *(const float4*)&g_hsrc[(size_t)si * D + 4 * sl];
        acc.x += al * h.x; acc.y += al * h.y; acc.z += al * h.z; acc.w += al * h.w;
    }
    s += __shfl_xor_sync(0xffffffffu, s, 16);
    acc.x += __shfl_xor_sync(0xffffffffu, acc.x, 16);
    acc.y += __shfl_xor_sync(0xffffffffu, acc.y, 16);
    acc.z += __shfl_xor_sync(0xffffffffu, acc.z, 16);
    acc.w += __shfl_xor_sync(0xffffffffu, acc.w, 16);
    float inv = 1.f / (s + 1e-16f);
    if (lane < 16)
        *(float4*)&g_agg[(size_t)w * D + 4 * sl] =
            make_float4(acc.x * inv, acc.y * inv, acc.z * inv, acc.w * inv);
}

// ---------------- K_mm2: out = feat_dst@W1 + agg@out_w[64:] + b (K=192) -----
// same pipeline; stages 0..15 from feat_dst, 16..23 from g_agg
#define KK2 (INC + D)
#define SMW2 (KK2 * 32 * 8 + STG * INC * CH * 4)    // 48KB + 16KB
__global__ void __launch_bounds__(256, 3)
k_mm2(const float* __restrict__ feat_dst, const float* __restrict__ out_w,
      const float* __restrict__ out_b, float* __restrict__ out, int n_rows) {
    extern __shared__ ull Ws2[];                 // [192 k][32 pairs]
    float* As = (float*)(Ws2 + KK2 * 32);
    uint32_t as_base = smem_u32(As);
    int t = threadIdx.x;
    const float4* w14 = (const float4*)g_W1;
    for (int i = t; i < INC * 16; i += 256) {
        float4 v = w14[i];
        int k = i >> 4, c4 = i & 15;
        Ws2[k * 32 + c4 * 2]     = pk2(v.x, v.y);
        Ws2[k * 32 + c4 * 2 + 1] = pk2(v.z, v.w);
    }
    const float4* ow4 = (const float4*)(out_w + (size_t)D * D);
    for (int i = t; i < D * 16; i += 256) {
        float4 v = ow4[i];
        int k = INC + (i >> 4), c4 = i & 15;
        Ws2[k * 32 + c4 * 2]     = pk2(v.x, v.y);
        Ws2[k * 32 + c4 * 2 + 1] = pk2(v.z, v.w);
    }
    int row0 = blockIdx.x * 128;
    int lrow = t >> 1, half = t & 1;
    int grow = row0 + lrow; if (grow > n_rows - 1) grow = n_rows - 1;
    const float* gsrc1 = feat_dst + (size_t)grow * INC + half * 4;
    const float* gsrc2 = g_agg + (size_t)grow * D + half * 4;
    uint32_t sdst = as_base + (lrow * CH + half * 4) * 4;
    const int NS = KK2 / CH;                     // 24 stages
    #pragma unroll
    for (int s = 0; s < 3; s++) {
        cpa16(sdst + (s % STG) * INC * CH * 4, gsrc1 + s * CH);
        CPA_COMMIT();
    }
    int tx = t & 7, ty = t >> 3;
    int cA = tx * 4, cB = 32 + tx * 4;
    float4 obA = *(const float4*)&out_b[cA];
    float4 obB = *(const float4*)&out_b[cB];
    ull acc[4][4];
    #pragma unroll
    for (int i = 0; i < 4; i++) {
        acc[i][0] = pk2(obA.x, obA.y); acc[i][1] = pk2(obA.z, obA.w);
        acc[i][2] = pk2(obB.x, obB.y); acc[i][3] = pk2(obB.z, obB.w);
    }
    for (int s = 0; s < NS; s++) {
        CPA_WAIT2();
        __syncthreads();
        int sn = s + 3;
        if (sn < NS) {
            if (sn < 16) cpa16(sdst + (sn % STG) * INC * CH * 4, gsrc1 + sn * CH);
            else         cpa16(sdst + (sn % STG) * INC * CH * 4, gsrc2 + (sn - 16) * CH);
        }
        CPA_COMMIT();
        const float* Ast = As + (s % STG) * INC * CH;
        #pragma unroll
        for (int j = 0; j < CH; j++) {
            int k = s * CH + j;
            ulonglong2 bA = *(const ulonglong2*)&Ws2[k * 32 + tx * 2];
            ulonglong2 bB = *(const ulonglong2*)&Ws2[k * 32 + 16 + tx * 2];
            #pragma unroll
            for (int i = 0; i < 4; i++) {
                float a = Ast[(ty + 32 * i) * CH + j];
                ull aa = pk2(a, a);
                fma2(acc[i][0], aa, bA.x); fma2(acc[i][1], aa, bA.y);
                fma2(acc[i][2], aa, bB.x); fma2(acc[i][3], aa, bB.y);
            }
        }
    }
    #pragma unroll
    for (int i = 0; i < 4; i++) {
        int r = row0 + ty + 32 * i;
        if (r < n_rows) {
            float2 p0 = up2(acc[i][0]), p1 = up2(acc[i][1]);
            float2 p2 = up2(acc[i][2]), p3 = up2(acc[i][3]);
            *(float4*)&out[(size_t)r * D + cA] = make_float4(p0.x, p0.y, p1.x, p1.y);
            *(float4*)&out[(size_t)r * D + cB] = make_float4(p2.x, p2.y, p3.x, p3.y);
        }
    }
}

// ---------------------------------------------------------------------------
extern "C" void kernel_launch(void* const* d_in, const int* in_sizes, int n_in,
                              void* d_out, int out_size) {
    const float* feat_src    = (const float*)d_in[0];
    const float* feat_dst    = (const float*)d_in[1];
    const float* edge_weight = (const float*)d_in[2];
    const int*   src_idx     = (const int*)d_in[3];
    const int*   dst_idx     = (const int*)d_in[4];
    const float* weight_n    = (const float*)d_in[5];
    const float* weight_e    = (const float*)d_in[6];
    const float* query       = (const float*)d_in[7];
    const float* key_w       = (const float*)d_in[8];
    const float* att_w       = (const float*)d_in[9];
    const float* att_b       = (const float*)d_in[10];
    const float* out_w       = (const float*)d_in[11];
    const float* out_b       = (const float*)d_in[12];
    float* out = (float*)d_out;

    int n_nodes = in_sizes[0] / INC;
    int n_edges = in_sizes[3];
    int nb = (n_nodes + 127) / 128;

    cudaFuncSetAttribute(k_mm1, cudaFuncAttributeMaxDynamicSharedMemorySize, SMW1);
    cudaFuncSetAttribute(k_mm2, cudaFuncAttributeMaxDynamicSharedMemorySize, SMW2);

    int prep_blocks = 33 + (n_edges + 1 + 255) / 256;
    k_prep<<<prep_blocks, 256>>>(weight_n, weight_e, query, key_w, att_w,
                                 out_w, dst_idx, n_nodes, n_edges);
    k_mm1<<<nb, 256, SMW1>>>(feat_src, weight_n, n_nodes);
    k_agg<<<(n_nodes * 32 + 255) / 256, 256>>>(src_idx, edge_weight, feat_dst,
                                               att_b, n_nodes);
    k_mm2<<<nb, 256, SMW2>>>(feat_dst, out_w, out_b, out, n_nodes);
}